// round 8
// baseline (speedup 1.0000x reference)
#include <cuda_runtime.h>
#include <cuda_fp16.h>
#include <math.h>
#include <stdint.h>

// ==========================================================================
// DepthAwareTokenAggregator — single-pass fp16 HMMA (sm_103-safe)
// R8: 512 thr/CTA, 64-reg budget, 2 CTAs/SM -> 32 warps/SM (occ 50%).
//     16 warps = 2 M x 8 N, per-warp m32 x n32. Triple-buffered B.
// ==========================================================================

#define SA_E   264u                // A row stride in fp16 elems (528B, odd granules)
#define SA_B   528u
#define STRB   80u                 // B row stride bytes (5 granules, odd)
#define OFF_B   33792u             // 64 * 528
#define BUFSZ   20480u             // 256 rows * 80B (one k=32 chunk)
#define OFF_SCR 95232u             // OFF_B + 3*BUFSZ
#define SMEM_TOTAL 100352u         // + 5120B scratch; x2 = 196.5KB/SM

__device__ __align__(16) __half g_Bh[256 * 256];

// W1[k][n] -> Bh[n][k] fp16 for k < 256 (k=256 slab handled in fp32 epilogue)
__global__ void prep_B(const float* __restrict__ W1) {
    int n = blockIdx.x, k = threadIdx.x;
    g_Bh[n * 256 + k] = __float2half_rn(W1[(size_t)k * 256 + n]);
}

__device__ __forceinline__ uint32_t smem_u32(const void* p) {
    uint32_t a;
    asm("{ .reg .u64 t; cvta.to.shared.u64 t, %1; cvt.u32.u64 %0, t; }" : "=r"(a) : "l"(p));
    return a;
}
__device__ __forceinline__ void mma16816(float* d, const uint32_t* a, const uint32_t* b) {
    asm volatile("mma.sync.aligned.m16n8k16.row.col.f32.f16.f16.f32 "
                 "{%0,%1,%2,%3}, {%4,%5,%6,%7}, {%8,%9}, {%0,%1,%2,%3};"
                 : "+f"(d[0]), "+f"(d[1]), "+f"(d[2]), "+f"(d[3])
                 : "r"(a[0]), "r"(a[1]), "r"(a[2]), "r"(a[3]), "r"(b[0]), "r"(b[1]));
}
__device__ __forceinline__ void ldmat4(uint32_t& r0, uint32_t& r1, uint32_t& r2, uint32_t& r3,
                                       uint32_t addr) {
    asm volatile("ldmatrix.sync.aligned.m8n8.x4.shared.b16 {%0,%1,%2,%3}, [%4];"
                 : "=r"(r0), "=r"(r1), "=r"(r2), "=r"(r3) : "r"(addr));
}
// GELU with Abramowitz-Stegun 7.1.26 erf (|eps| <= 1.5e-7)
__device__ __forceinline__ float gelu_f(float h) {
    float ax = fabsf(h) * 0.70710678118654752f;
    float t  = __fdividef(1.0f, fmaf(0.3275911f, ax, 1.0f));
    float p  = fmaf(t, 1.061405429f, -1.453152027f);
    p = fmaf(t, p, 1.421413741f);
    p = fmaf(t, p, -0.284496736f);
    p = fmaf(t, p, 0.254829592f);
    p = p * t;
    float e  = __expf(-ax * ax);
    float er = copysignf(fmaf(-p, e, 1.0f), h);
    return 0.5f * h * (1.0f + er);
}
// convert 4 floats to 2 packed fp16 pairs
__device__ __forceinline__ uint2 cvt4(float4 v) {
    uint2 r;
    __half a = __float2half_rn(v.x), b = __float2half_rn(v.y);
    __half c = __float2half_rn(v.z), d = __float2half_rn(v.w);
    r.x = (uint32_t)__half_as_ushort(a) | ((uint32_t)__half_as_ushort(b) << 16);
    r.y = (uint32_t)__half_as_ushort(c) | ((uint32_t)__half_as_ushort(d) << 16);
    return r;
}

// Load one k=32 B chunk into buffer buf via cp.async (512 threads).
__device__ __forceinline__ void issue_chunk(uint32_t sbase, int c, int buf) {
    const uint32_t dstb = sbase + OFF_B + (uint32_t)buf * BUFSZ;
    const int tid = threadIdx.x;
    #pragma unroll
    for (int i = 0; i < 2; ++i) {
        int op = i * 512 + tid;                  // 0..1023
        int n = op >> 2, q = op & 3;
        const void* src = g_Bh + (size_t)n * 256 + c * 32 + q * 8;
        uint32_t dst = dstb + (uint32_t)n * STRB + (uint32_t)q * 16u;
        asm volatile("cp.async.cg.shared.global [%0], [%1], 16;" :: "r"(dst), "l"(src));
    }
    asm volatile("cp.async.commit_group;" ::: "memory");
}

extern __shared__ char smem[];

__global__ __launch_bounds__(512, 2)
void dat_hmma_kernel(const float* __restrict__ sampled,   // [4096,64,256]
                     const float* __restrict__ valid,     // [4096,64]
                     const float* __restrict__ y_norm,    // [64]
                     const float* __restrict__ W1,        // [257,256]
                     const float* __restrict__ b1,        // [256]
                     const float* __restrict__ W2,        // [256]
                     const float* __restrict__ b2,        // [1]
                     float* __restrict__ out)             // [4096,256]
{
    const uint32_t sbase = smem_u32(smem);
    const int tid = threadIdx.x, wid = tid >> 5, lane = tid & 31;
    const int wm = wid & 1;                      // M-warp: rows wm*32..wm*32+31
    const int wn = wid >> 1;                     // N-warp: cols wn*32..wn*32+31
    const int bx = blockIdx.x;                   // token id

    float* spart = reinterpret_cast<float*>(smem + OFF_SCR);        // [8][64]
    float* slog  = spart + 512;                                      // [64]
    float* sval  = slog + 64;                                        // [64]
    float* swts  = sval + 64;                                        // [64]
    float* sW256 = swts + 64;                                        // [256]
    float* sY    = sW256 + 256;                                      // [64]
    float* sout  = sY + 64;                                          // [256]

    // kick off first two B chunks (bufs 0, 1)
    issue_chunk(sbase, 0, 0);
    issue_chunk(sbase, 1, 1);

    const float* src = sampled + (size_t)bx * 64 * 256;
    // per-thread A mapping: row = tid>>3 (0..63), one float4 (4 k) at (tid&7)
    const int arow = tid >> 3;
    const int afq  = tid & 7;                    // float4 index within a k=32 chunk
    const float4* asrc = reinterpret_cast<const float4*>(src + (size_t)arow * 256) + afq;
    const uint32_t abyte = (uint32_t)arow * SA_B + (uint32_t)afq * 8u;  // 4 fp16 = 8B

    // epilogue constants (scratch untouched by mainloop)
    if (tid < 256) sW256[tid] = W1[256 * 256 + tid];
    if (tid < 64) { sY[tid] = y_norm[tid]; sval[tid] = valid[(size_t)bx * 64 + tid]; }

    // ---- prologue: convert A chunk 0 (k 0..31) ----
    {
        uint2 h = cvt4(asrc[0]);
        *reinterpret_cast<uint2*>(smem + abyte) = h;
    }

    // ---- main loop: 8 chunks of k=32, triple-buffered B, one barrier/chunk ----
    float acc[2][4][4];
    #pragma unroll
    for (int a = 0; a < 2; ++a)
        #pragma unroll
        for (int b = 0; b < 4; ++b)
            #pragma unroll
            for (int d = 0; d < 4; ++d) acc[a][b][d] = 0.0f;

    const uint32_t a_lane = (uint32_t)(lane & 15) * SA_B + (uint32_t)(lane >> 4) * 16u;
    const uint32_t g = (uint32_t)(lane >> 3);
    const uint32_t nrow = (uint32_t)(wn * 32) + ((g >> 1) * 8u) + (uint32_t)(lane & 7);

    #pragma unroll 1
    for (int c = 0; c < 8; ++c) {
        if (c < 7) asm volatile("cp.async.wait_group 1;" ::: "memory");
        else       asm volatile("cp.async.wait_group 0;" ::: "memory");
        __syncthreads();   // chunk c visible; A chunk c stored; buf (c+2)%3 retired

        // refill pipeline (buffer (c+2)%3 free as of this barrier)
        if (c + 2 < 8) issue_chunk(sbase, c + 2, (c + 2) % 3);

        // prefetch next A chunk's gmem floats (hidden behind MMA)
        float4 pv;
        const bool do_conv = (c < 7);
        if (do_conv) pv = asrc[(c + 1) * 8];

        const uint32_t bbase = sbase + OFF_B + (uint32_t)(c % 3) * BUFSZ;

        #pragma unroll
        for (int ks = 0; ks < 2; ++ks) {
            uint32_t ah[2][4];
            #pragma unroll
            for (int mt = 0; mt < 2; ++mt) {
                uint32_t ab = (uint32_t)(wm * 32 + mt * 16) * SA_B
                            + (uint32_t)(c * 32 + ks * 16) * 2u + a_lane;
                ldmat4(ah[mt][0], ah[mt][1], ah[mt][2], ah[mt][3], sbase + ab);
            }
            const uint32_t kbyt = ((uint32_t)(ks * 16) + (g & 1) * 8u) * 2u;
            const uint32_t baddr = nrow * STRB + kbyt;

            uint32_t bb[4][2];
            ldmat4(bb[0][0], bb[0][1], bb[1][0], bb[1][1], bbase + baddr);
            ldmat4(bb[2][0], bb[2][1], bb[3][0], bb[3][1],
                   bbase + baddr + 16u * STRB);
            #pragma unroll
            for (int mt = 0; mt < 2; ++mt)
                #pragma unroll
                for (int nt = 0; nt < 4; ++nt) mma16816(acc[mt][nt], ah[mt], bb[nt]);
        }

        // convert + store next A chunk (regs -> smem); visible after next barrier
        if (do_conv) {
            *reinterpret_cast<uint2*>(smem + abyte + (uint32_t)(c + 1) * 64u) = cvt4(pv);
        }
    }

    // ---- epilogue: fp32 rank-1 y_norm term, bias + GELU + W2 dot ----
    const int r0 = wm * 32 + (lane >> 2);
    float s0[2] = {0.f, 0.f}, s1[2] = {0.f, 0.f};
    #pragma unroll
    for (int mt = 0; mt < 2; ++mt) {
        const float yv0 = sY[r0 + mt * 16];
        const float yv1 = sY[r0 + mt * 16 + 8];
        #pragma unroll
        for (int nt = 0; nt < 4; ++nt) {
            int col = wn * 32 + nt * 8 + 2 * (lane & 3);
            float2 wv  = *reinterpret_cast<const float2*>(&sW256[col]);
            float2 bbv = *reinterpret_cast<const float2*>(&b1[col]);
            float2 wwv = *reinterpret_cast<const float2*>(&W2[col]);
            float h0 = fmaf(yv0, wv.x, acc[mt][nt][0]) + bbv.x;
            float h1 = fmaf(yv0, wv.y, acc[mt][nt][1]) + bbv.y;
            float h2 = fmaf(yv1, wv.x, acc[mt][nt][2]) + bbv.x;
            float h3 = fmaf(yv1, wv.y, acc[mt][nt][3]) + bbv.y;
            s0[mt] += gelu_f(h0) * wwv.x;
            s0[mt] += gelu_f(h1) * wwv.y;
            s1[mt] += gelu_f(h2) * wwv.x;
            s1[mt] += gelu_f(h3) * wwv.y;
        }
    }
    #pragma unroll
    for (int mt = 0; mt < 2; ++mt) {
        s0[mt] += __shfl_xor_sync(0xffffffffu, s0[mt], 1);
        s0[mt] += __shfl_xor_sync(0xffffffffu, s0[mt], 2);
        s1[mt] += __shfl_xor_sync(0xffffffffu, s1[mt], 1);
        s1[mt] += __shfl_xor_sync(0xffffffffu, s1[mt], 2);
    }

    if ((lane & 3) == 0) {
        #pragma unroll
        for (int mt = 0; mt < 2; ++mt) {
            spart[wn * 64 + r0 + mt * 16]     = s0[mt];
            spart[wn * 64 + r0 + mt * 16 + 8] = s1[mt];
        }
    }
    __syncthreads();

    if (tid < 64) {
        float lg = b2[0];
        #pragma unroll
        for (int gg = 0; gg < 8; ++gg) lg += spart[gg * 64 + tid];
        if (sval[tid] < 0.5f) lg = -10000.0f;
        slog[tid] = lg;
    }
    __syncthreads();

    if (wid == 0) {                               // softmax over 64 y for this token
        float l0 = slog[lane], l1 = slog[32 + lane];
        float v0 = sval[lane], v1 = sval[32 + lane];
        float mx = fmaxf(l0, l1);
        #pragma unroll
        for (int s = 16; s > 0; s >>= 1) mx = fmaxf(mx, __shfl_xor_sync(0xffffffffu, mx, s));
        float e0 = expf(l0 - mx), e1 = expf(l1 - mx);
        float z = e0 + e1;
        #pragma unroll
        for (int s = 16; s > 0; s >>= 1) z += __shfl_xor_sync(0xffffffffu, z, s);
        float w0 = (e0 / z) * v0, w1 = (e1 / z) * v1;
        float s2 = w0 + w1;
        #pragma unroll
        for (int s = 16; s > 0; s >>= 1) s2 += __shfl_xor_sync(0xffffffffu, s2, s);
        float denom = fmaxf(s2, 1e-6f);
        swts[lane]      = w0 / denom;
        swts[32 + lane] = w1 / denom;
    }
    __syncthreads();

    // ---- out[bx][c] = sum_y w[y] * A_hi[y][c]; y split across 2 threads/col ----
    {
        const __half* Hi = reinterpret_cast<const __half*>(smem);
        const int t2 = tid >> 8, cc = tid & 255;
        float a = 0.f;
        #pragma unroll 8
        for (int y = t2 * 32; y < t2 * 32 + 32; ++y)
            a = fmaf(swts[y], __half2float(Hi[(uint32_t)y * SA_E + (uint32_t)cc]), a);
        if (t2 == 1) sout[cc] = a;
        __syncthreads();
        if (t2 == 0) out[(size_t)bx * 256 + cc] = a + sout[cc];
    }
}

extern "C" void kernel_launch(void* const* d_in, const int* in_sizes, int n_in,
                              void* d_out, int out_size) {
    (void)in_sizes; (void)n_in; (void)out_size;
    const float* sampled = (const float*)d_in[0];
    const float* valid   = (const float*)d_in[1];
    const float* y_norm  = (const float*)d_in[2];
    const float* W1      = (const float*)d_in[3];
    const float* b1      = (const float*)d_in[4];
    const float* W2      = (const float*)d_in[5];
    const float* b2      = (const float*)d_in[6];

    prep_B<<<256, 256>>>(W1);

    cudaFuncSetAttribute(dat_hmma_kernel, cudaFuncAttributeMaxDynamicSharedMemorySize, SMEM_TOTAL);
    dat_hmma_kernel<<<4096, 512, SMEM_TOTAL>>>(sampled, valid, y_norm, W1, b1, W2, b2, (float*)d_out);
}